// round 13
// baseline (speedup 1.0000x reference)
#include <cuda_runtime.h>
#include <stdint.h>
#include <float.h>

#define NROWS 8192
#define NCOLS 1000
#define NT 256
#define WPB 8                 // warps (rows) per block
#define NB (NROWS / WPB)      // 1024 blocks
#define NQ 20
// r[0..5]   : M_j = max over non-target columns, per source
// r[6]      : sum e^{s}
// r[7]      : sum e^{s/T}
// r[8+j]    : S1_j = sum e^{x_j/T}
// r[14+j]   : S2_j = sum e^{x_j/T} * (s/T)

__device__ float g_ce[NROWS];
__device__ float g_a[NROWS];
__device__ float g_mx[NROWS];
__device__ int   g_ticket;    // zero-init; reset by last block each run

__device__ __forceinline__ void combine20(float* r, const float* t) {
#pragma unroll
    for (int j = 0; j < 6; j++) r[j] = fmaxf(r[j], t[j]);
#pragma unroll
    for (int i = 6; i < NQ; i++) r[i] += t[i];
}

__global__ __launch_bounds__(NT, 5)
void fused_kernel(const float* __restrict__ t1, const float* __restrict__ t2,
                  const float* __restrict__ t3, const float* __restrict__ t4,
                  const float* __restrict__ t5, const float* __restrict__ os,
                  const int* __restrict__ tg, float* __restrict__ out) {
    const int tid  = threadIdx.x;
    const int lane = tid & 31;
    const int wid  = tid >> 5;
    const int row  = blockIdx.x * WPB + wid;
    const long base = (long)row * NCOLS;
    const int target = __ldg(tg + row);   // warp-uniform -> UR

    const float INV_T   = 0.05f;   // 1/T_KD
    const float T2      = 400.f;   // T_KD^2
    const float INV_TTH = 0.5f;    // 1/T_TH

    float r[NQ];
#pragma unroll
    for (int i = 0; i < 6; i++) r[i] = -FLT_MAX;
#pragma unroll
    for (int i = 6; i < NQ; i++) r[i] = 0.f;

    const float4* p0 = (const float4*)(t1 + base);
    const float4* p1 = (const float4*)(t2 + base);
    const float4* p2 = (const float4*)(t3 + base);
    const float4* p3 = (const float4*)(t4 + base);
    const float4* p4 = (const float4*)(t5 + base);
    const float4* ps = (const float4*)(os + base);

#define BODY(q)                                                               \
    {                                                                         \
        float4 v0 = __ldg(p0 + (q));                                          \
        float4 v1 = __ldg(p1 + (q));                                          \
        float4 v2 = __ldg(p2 + (q));                                          \
        float4 v3 = __ldg(p3 + (q));                                          \
        float4 v4 = __ldg(p4 + (q));                                          \
        float4 vs = __ldg(ps + (q));                                          \
        const int c0_ = (q) * 4;                                              \
        float a0[4] = {v0.x, v0.y, v0.z, v0.w};                               \
        float a1[4] = {v1.x, v1.y, v1.z, v1.w};                               \
        float a2[4] = {v2.x, v2.y, v2.z, v2.w};                               \
        float a3[4] = {v3.x, v3.y, v3.z, v3.w};                               \
        float a4[4] = {v4.x, v4.y, v4.z, v4.w};                               \
        float as[4] = {vs.x, vs.y, vs.z, vs.w};                               \
        _Pragma("unroll")                                                     \
        for (int k = 0; k < 4; k++) {                                         \
            const bool isT = (c0_ + k == target);                             \
            float m = (a0[k] + a1[k] + a2[k] + a3[k] + a4[k]) * 0.2f;         \
            float lpw = as[k] * INV_T;                                        \
            r[6] += __expf(as[k]);                                            \
            r[7] += __expf(lpw);                                              \
            float x[6] = {a0[k], a1[k], a2[k], a3[k], a4[k], m};              \
            _Pragma("unroll")                                                 \
            for (int j = 0; j < 6; j++) {                                     \
                float xv = x[j];                                              \
                float e = __expf(xv * INV_T);                                 \
                r[8 + j] += e;                                                \
                r[14 + j] = fmaf(e, lpw, r[14 + j]);                          \
                r[j] = fmaxf(r[j], isT ? -FLT_MAX : xv);                      \
            }                                                                 \
        }                                                                     \
    }

    // 7 full iterations: warp covers float4[0..223]
#pragma unroll 2
    for (int it = 0; it < 7; it++) {
        BODY(it * 32 + lane)
    }
    // tail: float4[224..249] (26 lanes)
    if (lane < 26) {
        BODY(224 + lane)
    }
#undef BODY

    // ---- Target logits (deferred; uniform address per warp) ----
    float tq[7];
    tq[0] = __ldg(t1 + base + target);
    tq[1] = __ldg(t2 + base + target);
    tq[2] = __ldg(t3 + base + target);
    tq[3] = __ldg(t4 + base + target);
    tq[4] = __ldg(t5 + base + target);
    tq[6] = __ldg(os + base + target);
    tq[5] = (tq[0] + tq[1] + tq[2] + tq[3] + tq[4]) * 0.2f;  // same assoc as BODY

    // ---- Single warp-level reduction of all 20 quantities ----
#pragma unroll
    for (int o = 16; o > 0; o >>= 1) {
        float t[NQ];
#pragma unroll
        for (int i = 0; i < NQ; i++) t[i] = __shfl_xor_sync(0xffffffffu, r[i], o);
        combine20(r, t);
    }

    if (lane == 0) {
        float CE   = __logf(r[6]) - tq[6];
        float lseT = __logf(r[7]);

        // full-row max per teacher = max(M_j, tq_j)
        float tmax = fmaxf(r[0], tq[0]);
#pragma unroll
        for (int j = 1; j < 5; j++) tmax = fmaxf(tmax, fmaxf(r[j], tq[j]));

        float margins[6], kd[6];
#pragma unroll
        for (int j = 0; j < 6; j++) {
            kd[j]      = -T2 * (r[14 + j] / r[8 + j] - lseT);
            margins[j] = fmaxf(tq[j] - r[j], 0.f);
        }
        float mm = margins[0];
#pragma unroll
        for (int j = 1; j < 6; j++) mm = fmaxf(mm, margins[j]);
        float se = 0.f, A = 0.f;
#pragma unroll
        for (int j = 0; j < 6; j++) {
            float e = __expf((margins[j] - mm) * INV_TTH);
            se += e;
            A  += e * tq[j] * (kd[j] - CE);
        }
        g_ce[row] = CE;
        g_a[row]  = A / se;
        g_mx[row] = tmax;
        __threadfence();   // order this row's results before the ticket bump
    }

    // ---- last-block finalize ----
    __shared__ bool amLast;
    __shared__ float s1[WPB], s2[WPB], s3[WPB];
    __syncthreads();
    if (tid == 0) {
        int t = atomicAdd(&g_ticket, 1);
        amLast = (t == NB - 1);
    }
    __syncthreads();
    if (!amLast) return;
    __threadfence();

    const float4* c4 = (const float4*)g_ce;
    const float4* a4 = (const float4*)g_a;
    const float4* m4 = (const float4*)g_mx;

    float ce = 0.f, a = 0.f, mx = -FLT_MAX;
#pragma unroll
    for (int i = 0; i < 8; i++) {          // 2048 float4 per array / 256 threads
        int idx = tid + i * NT;
        float4 c = c4[idx], aa = a4[idx], m = m4[idx];
        ce += (c.x + c.y) + (c.z + c.w);
        a  += (aa.x + aa.y) + (aa.z + aa.w);
        mx  = fmaxf(mx, fmaxf(fmaxf(m.x, m.y), fmaxf(m.z, m.w)));
    }
#pragma unroll
    for (int o = 16; o > 0; o >>= 1) {
        ce += __shfl_xor_sync(0xffffffffu, ce, o);
        a  += __shfl_xor_sync(0xffffffffu, a, o);
        mx  = fmaxf(mx, __shfl_xor_sync(0xffffffffu, mx, o));
    }
    if (lane == 0) { s1[wid] = ce; s2[wid] = a; s3[wid] = mx; }
    __syncthreads();
    if (wid == 0) {
        ce = (lane < WPB) ? s1[lane] : 0.f;
        a  = (lane < WPB) ? s2[lane] : 0.f;
        mx = (lane < WPB) ? s3[lane] : -FLT_MAX;
#pragma unroll
        for (int o = 4; o > 0; o >>= 1) {
            ce += __shfl_xor_sync(0xffffffffu, ce, o);
            a  += __shfl_xor_sync(0xffffffffu, a, o);
            mx  = fmaxf(mx, __shfl_xor_sync(0xffffffffu, mx, o));
        }
        if (lane == 0) {
            const float invB = 1.0f / (float)NROWS;
            out[0] = ce * invB + (0.8f / mx) * (a * invB);
            g_ticket = 0;   // reset for next graph replay (deterministic)
        }
    }
}

extern "C" void kernel_launch(void* const* d_in, const int* in_sizes, int n_in,
                              void* d_out, int out_size) {
    const float* t1 = (const float*)d_in[0];
    const float* t2 = (const float*)d_in[1];
    const float* t3 = (const float*)d_in[2];
    const float* t4 = (const float*)d_in[3];
    const float* t5 = (const float*)d_in[4];
    const float* os = (const float*)d_in[5];
    const int*   tg = (const int*)d_in[6];

    fused_kernel<<<NB, NT>>>(t1, t2, t3, t4, t5, os, tg, (float*)d_out);
}

// round 14
// speedup vs baseline: 1.2085x; 1.2085x over previous
#include <cuda_runtime.h>
#include <stdint.h>
#include <float.h>

#define NROWS 8192
#define NCOLS 1000
#define NT 256
#define WPB 8                 // warps (rows) per block
#define NB (NROWS / WPB)      // 1024 blocks
#define NQ 20
// r[0..5]   : M_j = max over non-target columns, per source
// r[6]      : sum e^{s}
// r[7]      : sum e^{s/T}
// r[8+j]    : S1_j = sum e^{x_j/T}
// r[14+j]   : S2_j = sum e^{x_j/T} * (s/T)

__device__ float g_ce[NROWS];
__device__ float g_a[NROWS];
__device__ float g_mx[NROWS];
__device__ int   g_ticket;    // zero-init; reset by last block each run

__device__ __forceinline__ void combine20(float* r, const float* t) {
#pragma unroll
    for (int j = 0; j < 6; j++) r[j] = fmaxf(r[j], t[j]);
#pragma unroll
    for (int i = 6; i < NQ; i++) r[i] += t[i];
}

__global__ __launch_bounds__(NT, 4)
void fused_kernel(const float* __restrict__ t1, const float* __restrict__ t2,
                  const float* __restrict__ t3, const float* __restrict__ t4,
                  const float* __restrict__ t5, const float* __restrict__ os,
                  const int* __restrict__ tg, float* __restrict__ out) {
    const int tid  = threadIdx.x;
    const int lane = tid & 31;
    const int wid  = tid >> 5;
    const int row  = blockIdx.x * WPB + wid;
    const long base = (long)row * NCOLS;
    const int target = __ldg(tg + row);   // warp-uniform -> UR

    const float INV_T   = 0.05f;   // 1/T_KD
    const float T2      = 400.f;   // T_KD^2
    const float INV_TTH = 0.5f;    // 1/T_TH

    float r[NQ];
#pragma unroll
    for (int i = 0; i < 6; i++) r[i] = -FLT_MAX;
#pragma unroll
    for (int i = 6; i < NQ; i++) r[i] = 0.f;

    const float4* p0 = (const float4*)(t1 + base);
    const float4* p1 = (const float4*)(t2 + base);
    const float4* p2 = (const float4*)(t3 + base);
    const float4* p3 = (const float4*)(t4 + base);
    const float4* p4 = (const float4*)(t5 + base);
    const float4* ps = (const float4*)(os + base);

#define BODY(q)                                                               \
    {                                                                         \
        float4 v0 = __ldg(p0 + (q));                                          \
        float4 v1 = __ldg(p1 + (q));                                          \
        float4 v2 = __ldg(p2 + (q));                                          \
        float4 v3 = __ldg(p3 + (q));                                          \
        float4 v4 = __ldg(p4 + (q));                                          \
        float4 vs = __ldg(ps + (q));                                          \
        const int c0_ = (q) * 4;                                              \
        float a0[4] = {v0.x, v0.y, v0.z, v0.w};                               \
        float a1[4] = {v1.x, v1.y, v1.z, v1.w};                               \
        float a2[4] = {v2.x, v2.y, v2.z, v2.w};                               \
        float a3[4] = {v3.x, v3.y, v3.z, v3.w};                               \
        float a4[4] = {v4.x, v4.y, v4.z, v4.w};                               \
        float as[4] = {vs.x, vs.y, vs.z, vs.w};                               \
        _Pragma("unroll")                                                     \
        for (int k = 0; k < 4; k++) {                                         \
            const bool isT = (c0_ + k == target);                             \
            float m = (a0[k] + a1[k] + a2[k] + a3[k] + a4[k]) * 0.2f;         \
            float lpw = as[k] * INV_T;                                        \
            r[6] += __expf(as[k]);                                            \
            r[7] += __expf(lpw);                                              \
            float x[6] = {a0[k], a1[k], a2[k], a3[k], a4[k], m};              \
            _Pragma("unroll")                                                 \
            for (int j = 0; j < 6; j++) {                                     \
                float xv = x[j];                                              \
                float e = __expf(xv * INV_T);                                 \
                r[8 + j] += e;                                                \
                r[14 + j] = fmaf(e, lpw, r[14 + j]);                          \
                r[j] = fmaxf(r[j], isT ? -FLT_MAX : xv);                      \
            }                                                                 \
        }                                                                     \
    }

    // 7 full iterations: warp covers float4[0..223]
#pragma unroll 2
    for (int it = 0; it < 7; it++) {
        BODY(it * 32 + lane)
    }
    // tail: float4[224..249] (26 lanes)
    if (lane < 26) {
        BODY(224 + lane)
    }
#undef BODY

    // ---- Target logits (deferred; uniform address per warp) ----
    float tq[7];
    tq[0] = __ldg(t1 + base + target);
    tq[1] = __ldg(t2 + base + target);
    tq[2] = __ldg(t3 + base + target);
    tq[3] = __ldg(t4 + base + target);
    tq[4] = __ldg(t5 + base + target);
    tq[6] = __ldg(os + base + target);
    tq[5] = (tq[0] + tq[1] + tq[2] + tq[3] + tq[4]) * 0.2f;  // same assoc as BODY

    // ---- Single warp-level reduction of all 20 quantities ----
#pragma unroll
    for (int o = 16; o > 0; o >>= 1) {
        float t[NQ];
#pragma unroll
        for (int i = 0; i < NQ; i++) t[i] = __shfl_xor_sync(0xffffffffu, r[i], o);
        combine20(r, t);
    }

    if (lane == 0) {
        float CE   = __logf(r[6]) - tq[6];
        float lseT = __logf(r[7]);

        // full-row max per teacher = max(M_j, tq_j)
        float tmax = fmaxf(r[0], tq[0]);
#pragma unroll
        for (int j = 1; j < 5; j++) tmax = fmaxf(tmax, fmaxf(r[j], tq[j]));

        float margins[6], kd[6];
#pragma unroll
        for (int j = 0; j < 6; j++) {
            kd[j]      = -T2 * (r[14 + j] / r[8 + j] - lseT);
            margins[j] = fmaxf(tq[j] - r[j], 0.f);
        }
        float mm = margins[0];
#pragma unroll
        for (int j = 1; j < 6; j++) mm = fmaxf(mm, margins[j]);
        float se = 0.f, A = 0.f;
#pragma unroll
        for (int j = 0; j < 6; j++) {
            float e = __expf((margins[j] - mm) * INV_TTH);
            se += e;
            A  += e * tq[j] * (kd[j] - CE);
        }
        g_ce[row] = CE;
        g_a[row]  = A / se;
        g_mx[row] = tmax;
        __threadfence();   // order this row's results before the ticket bump
    }

    // ---- last-block finalize ----
    __shared__ bool amLast;
    __shared__ float s1[WPB], s2[WPB], s3[WPB];
    __syncthreads();
    if (tid == 0) {
        int t = atomicAdd(&g_ticket, 1);
        amLast = (t == NB - 1);
    }
    __syncthreads();
    if (!amLast) return;
    __threadfence();

    const float4* c4 = (const float4*)g_ce;
    const float4* a4 = (const float4*)g_a;
    const float4* m4 = (const float4*)g_mx;

    float ce = 0.f, a = 0.f, mx = -FLT_MAX;
#pragma unroll
    for (int i = 0; i < 8; i++) {          // 2048 float4 per array / 256 threads
        int idx = tid + i * NT;
        float4 c = c4[idx], aa = a4[idx], m = m4[idx];
        ce += (c.x + c.y) + (c.z + c.w);
        a  += (aa.x + aa.y) + (aa.z + aa.w);
        mx  = fmaxf(mx, fmaxf(fmaxf(m.x, m.y), fmaxf(m.z, m.w)));
    }
#pragma unroll
    for (int o = 16; o > 0; o >>= 1) {
        ce += __shfl_xor_sync(0xffffffffu, ce, o);
        a  += __shfl_xor_sync(0xffffffffu, a, o);
        mx  = fmaxf(mx, __shfl_xor_sync(0xffffffffu, mx, o));
    }
    if (lane == 0) { s1[wid] = ce; s2[wid] = a; s3[wid] = mx; }
    __syncthreads();
    if (wid == 0) {
        ce = (lane < WPB) ? s1[lane] : 0.f;
        a  = (lane < WPB) ? s2[lane] : 0.f;
        mx = (lane < WPB) ? s3[lane] : -FLT_MAX;
#pragma unroll
        for (int o = 4; o > 0; o >>= 1) {
            ce += __shfl_xor_sync(0xffffffffu, ce, o);
            a  += __shfl_xor_sync(0xffffffffu, a, o);
            mx  = fmaxf(mx, __shfl_xor_sync(0xffffffffu, mx, o));
        }
        if (lane == 0) {
            const float invB = 1.0f / (float)NROWS;
            out[0] = ce * invB + (0.8f / mx) * (a * invB);
            g_ticket = 0;   // reset for next graph replay (deterministic)
        }
    }
}

extern "C" void kernel_launch(void* const* d_in, const int* in_sizes, int n_in,
                              void* d_out, int out_size) {
    const float* t1 = (const float*)d_in[0];
    const float* t2 = (const float*)d_in[1];
    const float* t3 = (const float*)d_in[2];
    const float* t4 = (const float*)d_in[3];
    const float* t5 = (const float*)d_in[4];
    const float* os = (const float*)d_in[5];
    const int*   tg = (const int*)d_in[6];

    fused_kernel<<<NB, NT>>>(t1, t2, t3, t4, t5, os, tg, (float*)d_out);
}

// round 15
// speedup vs baseline: 1.2950x; 1.0716x over previous
#include <cuda_runtime.h>
#include <stdint.h>
#include <float.h>

#define NROWS 8192
#define NCOLS 1000
#define NT 256
#define WPB 8                    // warps per block
#define NB1 592                  // 148 SMs x 4 CTAs: exactly one wave
#define GWARPS (NB1 * WPB)       // 4736 warp slots
#define NCHUNK (NROWS * 4)       // 32768 quarter-row chunks
#define NQ 20
#define NB2 32                   // combine kernel blocks (32 x 256 = 8192 rows)
// per-chunk quantities:
// r[0..5]   : M_j = max over non-target columns, per source
// r[6]      : sum e^{s}
// r[7]      : sum e^{s/T}
// r[8+j]    : S1_j = sum e^{x_j/T}
// r[14+j]   : S2_j = sum e^{x_j/T} * (s/T)

__device__ float g_part[NCHUNK * NQ];   // 2.62 MB chunk partials
__device__ float g_ce[NROWS];
__device__ float g_a[NROWS];
__device__ float g_mx[NROWS];
__device__ int   g_ticket;              // zero-init; reset by last block of kernel2

__global__ __launch_bounds__(NT, 4)
void part_kernel(const float* __restrict__ t1, const float* __restrict__ t2,
                 const float* __restrict__ t3, const float* __restrict__ t4,
                 const float* __restrict__ t5, const float* __restrict__ os,
                 const int* __restrict__ tg) {
    const int lane = threadIdx.x & 31;
    const int wid  = threadIdx.x >> 5;
    const int gw   = blockIdx.x * WPB + wid;   // global warp id

    const float INV_T = 0.05f;   // 1/T_KD

    // Static stride over chunks: 6 or 7 per warp (imbalance 1.2%)
    for (int c = gw; c < NCHUNK; c += GWARPS) {
        const int row = c >> 2;
        const int p   = c & 3;                 // quarter index
        const long base = (long)row * NCOLS;
        const int target = __ldg(tg + row);    // warp-uniform

        const float4* p0 = (const float4*)(t1 + base);
        const float4* p1 = (const float4*)(t2 + base);
        const float4* p2 = (const float4*)(t3 + base);
        const float4* p3 = (const float4*)(t4 + base);
        const float4* p4 = (const float4*)(t5 + base);
        const float4* ps = (const float4*)(os + base);

        float r[NQ];
#pragma unroll
        for (int i = 0; i < 6; i++) r[i] = -FLT_MAX;
#pragma unroll
        for (int i = 6; i < NQ; i++) r[i] = 0.f;

#define BODY(q)                                                               \
    {                                                                         \
        float4 v0 = __ldg(p0 + (q));                                          \
        float4 v1 = __ldg(p1 + (q));                                          \
        float4 v2 = __ldg(p2 + (q));                                          \
        float4 v3 = __ldg(p3 + (q));                                          \
        float4 v4 = __ldg(p4 + (q));                                          \
        float4 vs = __ldg(ps + (q));                                          \
        const int c0_ = (q) * 4;                                              \
        float a0[4] = {v0.x, v0.y, v0.z, v0.w};                               \
        float a1[4] = {v1.x, v1.y, v1.z, v1.w};                               \
        float a2[4] = {v2.x, v2.y, v2.z, v2.w};                               \
        float a3[4] = {v3.x, v3.y, v3.z, v3.w};                               \
        float a4[4] = {v4.x, v4.y, v4.z, v4.w};                               \
        float as[4] = {vs.x, vs.y, vs.z, vs.w};                               \
        _Pragma("unroll")                                                     \
        for (int k = 0; k < 4; k++) {                                         \
            const bool isT = (c0_ + k == target);                             \
            float m = (a0[k] + a1[k] + a2[k] + a3[k] + a4[k]) * 0.2f;         \
            float lpw = as[k] * INV_T;                                        \
            r[6] += __expf(as[k]);                                            \
            r[7] += __expf(lpw);                                              \
            float x[6] = {a0[k], a1[k], a2[k], a3[k], a4[k], m};              \
            _Pragma("unroll")                                                 \
            for (int j = 0; j < 6; j++) {                                     \
                float xv = x[j];                                              \
                float e = __expf(xv * INV_T);                                 \
                r[8 + j] += e;                                                \
                r[14 + j] = fmaf(e, lpw, r[14 + j]);                          \
                r[j] = fmaxf(r[j], isT ? -FLT_MAX : xv);                      \
            }                                                                 \
        }                                                                     \
    }

        const int q0 = p * 64 + lane;
        BODY(q0)
        if (p < 3 || lane < 26) {              // p==3 second half: float4[224..249]
            BODY(q0 + 32)
        }
#undef BODY

        // Per-chunk warp reduction of all 20 quantities
#pragma unroll
        for (int o = 16; o > 0; o >>= 1) {
            float t[NQ];
#pragma unroll
            for (int i = 0; i < NQ; i++) t[i] = __shfl_xor_sync(0xffffffffu, r[i], o);
#pragma unroll
            for (int j = 0; j < 6; j++) r[j] = fmaxf(r[j], t[j]);
#pragma unroll
            for (int i = 6; i < NQ; i++) r[i] += t[i];
        }

        // Lane 0 writes 20 contiguous floats (5 aligned 128-bit stores)
        if (lane == 0) {
            float4* dst = (float4*)(g_part + (size_t)c * NQ);
            dst[0] = make_float4(r[0],  r[1],  r[2],  r[3]);
            dst[1] = make_float4(r[4],  r[5],  r[6],  r[7]);
            dst[2] = make_float4(r[8],  r[9],  r[10], r[11]);
            dst[3] = make_float4(r[12], r[13], r[14], r[15]);
            dst[4] = make_float4(r[16], r[17], r[18], r[19]);
        }
    }
}

__global__ __launch_bounds__(NT)
void combine_kernel(const float* __restrict__ t1, const float* __restrict__ t2,
                    const float* __restrict__ t3, const float* __restrict__ t4,
                    const float* __restrict__ t5, const float* __restrict__ os,
                    const int* __restrict__ tg, float* __restrict__ out) {
    const int tid  = threadIdx.x;
    const int lane = tid & 31;
    const int wid  = tid >> 5;
    const int row  = blockIdx.x * NT + tid;

    const float T2      = 400.f;   // T_KD^2
    const float INV_TTH = 0.5f;    // 1/T_TH

    {
        // Combine 4 chunk partials (80 contiguous floats per row)
        const float4* src = (const float4*)(g_part + (size_t)row * 4 * NQ);
        float r[NQ];
#pragma unroll
        for (int i = 0; i < 6; i++) r[i] = -FLT_MAX;
#pragma unroll
        for (int i = 6; i < NQ; i++) r[i] = 0.f;
#pragma unroll
        for (int cpart = 0; cpart < 4; cpart++) {
            float v[NQ];
#pragma unroll
            for (int u = 0; u < 5; u++) {
                float4 f = src[cpart * 5 + u];
                v[u * 4 + 0] = f.x; v[u * 4 + 1] = f.y;
                v[u * 4 + 2] = f.z; v[u * 4 + 3] = f.w;
            }
#pragma unroll
            for (int j = 0; j < 6; j++) r[j] = fmaxf(r[j], v[j]);
#pragma unroll
            for (int i = 6; i < NQ; i++) r[i] += v[i];
        }

        const long base = (long)row * NCOLS;
        const int target = __ldg(tg + row);
        float tq[7];
        tq[0] = __ldg(t1 + base + target);
        tq[1] = __ldg(t2 + base + target);
        tq[2] = __ldg(t3 + base + target);
        tq[3] = __ldg(t4 + base + target);
        tq[4] = __ldg(t5 + base + target);
        tq[6] = __ldg(os + base + target);
        tq[5] = (tq[0] + tq[1] + tq[2] + tq[3] + tq[4]) * 0.2f;  // same assoc as BODY

        float CE   = __logf(r[6]) - tq[6];
        float lseT = __logf(r[7]);

        float tmax = fmaxf(r[0], tq[0]);
#pragma unroll
        for (int j = 1; j < 5; j++) tmax = fmaxf(tmax, fmaxf(r[j], tq[j]));

        float margins[6], kd[6];
#pragma unroll
        for (int j = 0; j < 6; j++) {
            kd[j]      = -T2 * (r[14 + j] / r[8 + j] - lseT);
            margins[j] = fmaxf(tq[j] - r[j], 0.f);
        }
        float mm = margins[0];
#pragma unroll
        for (int j = 1; j < 6; j++) mm = fmaxf(mm, margins[j]);
        float se = 0.f, A = 0.f;
#pragma unroll
        for (int j = 0; j < 6; j++) {
            float e = __expf((margins[j] - mm) * INV_TTH);
            se += e;
            A  += e * tq[j] * (kd[j] - CE);
        }
        g_ce[row] = CE;
        g_a[row]  = A / se;
        g_mx[row] = tmax;
    }
    __threadfence();   // order row results before the ticket bump

    // ---- last-block finalize ----
    __shared__ bool amLast;
    __shared__ float s1[WPB], s2[WPB], s3[WPB];
    __syncthreads();
    if (tid == 0) {
        int t = atomicAdd(&g_ticket, 1);
        amLast = (t == NB2 - 1);
    }
    __syncthreads();
    if (!amLast) return;
    __threadfence();

    const float4* c4 = (const float4*)g_ce;
    const float4* a4 = (const float4*)g_a;
    const float4* m4 = (const float4*)g_mx;

    float ce = 0.f, a = 0.f, mx = -FLT_MAX;
#pragma unroll
    for (int i = 0; i < 8; i++) {          // 2048 float4 per array / 256 threads
        int idx = tid + i * NT;
        float4 c = c4[idx], aa = a4[idx], m = m4[idx];
        ce += (c.x + c.y) + (c.z + c.w);
        a  += (aa.x + aa.y) + (aa.z + aa.w);
        mx  = fmaxf(mx, fmaxf(fmaxf(m.x, m.y), fmaxf(m.z, m.w)));
    }
#pragma unroll
    for (int o = 16; o > 0; o >>= 1) {
        ce += __shfl_xor_sync(0xffffffffu, ce, o);
        a  += __shfl_xor_sync(0xffffffffu, a, o);
        mx  = fmaxf(mx, __shfl_xor_sync(0xffffffffu, mx, o));
    }
    if (lane == 0) { s1[wid] = ce; s2[wid] = a; s3[wid] = mx; }
    __syncthreads();
    if (wid == 0) {
        ce = (lane < WPB) ? s1[lane] : 0.f;
        a  = (lane < WPB) ? s2[lane] : 0.f;
        mx = (lane < WPB) ? s3[lane] : -FLT_MAX;
#pragma unroll
        for (int o = 4; o > 0; o >>= 1) {
            ce += __shfl_xor_sync(0xffffffffu, ce, o);
            a  += __shfl_xor_sync(0xffffffffu, a, o);
            mx  = fmaxf(mx, __shfl_xor_sync(0xffffffffu, mx, o));
        }
        if (lane == 0) {
            const float invB = 1.0f / (float)NROWS;
            out[0] = ce * invB + (0.8f / mx) * (a * invB);
            g_ticket = 0;   // reset for next graph replay (deterministic)
        }
    }
}

extern "C" void kernel_launch(void* const* d_in, const int* in_sizes, int n_in,
                              void* d_out, int out_size) {
    const float* t1 = (const float*)d_in[0];
    const float* t2 = (const float*)d_in[1];
    const float* t3 = (const float*)d_in[2];
    const float* t4 = (const float*)d_in[3];
    const float* t5 = (const float*)d_in[4];
    const float* os = (const float*)d_in[5];
    const int*   tg = (const int*)d_in[6];

    part_kernel<<<NB1, NT>>>(t1, t2, t3, t4, t5, os, tg);
    combine_kernel<<<NB2, NT>>>(t1, t2, t3, t4, t5, os, tg, (float*)d_out);
}